// round 2
// baseline (speedup 1.0000x reference)
#include <cuda_runtime.h>
#include <cuda_bf16.h>

// KL(p||q) for diagonal Gaussians, mean over batch. Single fused kernel:
// grid-stride float4 elementwise + block reduce -> g_partials, then the
// last block (ticket via atomicAdd) reduces all partials in a FIXED order
// (deterministic) and writes the scalar. Counter self-resets for graph replay.

#define NBLOCKS 1024
#define NTHREADS 256

__device__ float g_partials[NBLOCKS];
__device__ unsigned int g_ticket = 0;

__device__ __forceinline__ float kl_term(float pm, float pl, float qm, float ql)
{
    float lr = ql - pl;
    float dm = pm - qm;
    return lr + __expf(-lr) + dm * dm * __expf(-ql) - 1.0f;
}

__device__ __forceinline__ float kl_vec4(float4 a, float4 b, float4 c, float4 d)
{
    return kl_term(a.x, b.x, c.x, d.x)
         + kl_term(a.y, b.y, c.y, d.y)
         + kl_term(a.z, b.z, c.z, d.z)
         + kl_term(a.w, b.w, c.w, d.w);
}

__global__ __launch_bounds__(NTHREADS) void kl_fused_kernel(
    const float* __restrict__ p_mu,
    const float* __restrict__ p_lv,
    const float* __restrict__ q_mu,
    const float* __restrict__ q_lv,
    float* __restrict__ out,
    int n4, float scale)
{
    const float4* pm4 = reinterpret_cast<const float4*>(p_mu);
    const float4* pl4 = reinterpret_cast<const float4*>(p_lv);
    const float4* qm4 = reinterpret_cast<const float4*>(q_mu);
    const float4* ql4 = reinterpret_cast<const float4*>(q_lv);

    const int tid    = blockIdx.x * blockDim.x + threadIdx.x;
    const int stride = gridDim.x * blockDim.x;

    float acc = 0.0f;
    int i = tid;
    // 2x unroll: 8 independent float4 loads in flight per iteration pair.
    for (; i + stride < n4; i += 2 * stride) {
        float4 a0 = pm4[i];
        float4 b0 = pl4[i];
        float4 c0 = qm4[i];
        float4 d0 = ql4[i];
        float4 a1 = pm4[i + stride];
        float4 b1 = pl4[i + stride];
        float4 c1 = qm4[i + stride];
        float4 d1 = ql4[i + stride];
        acc += kl_vec4(a0, b0, c0, d0);
        acc += kl_vec4(a1, b1, c1, d1);
    }
    for (; i < n4; i += stride) {
        acc += kl_vec4(pm4[i], pl4[i], qm4[i], ql4[i]);
    }

    // Block reduce
    #pragma unroll
    for (int off = 16; off > 0; off >>= 1)
        acc += __shfl_down_sync(0xFFFFFFFFu, acc, off);

    __shared__ float smem[NTHREADS / 32];
    __shared__ bool s_is_last;
    const int lane = threadIdx.x & 31;
    const int warp = threadIdx.x >> 5;
    if (lane == 0) smem[warp] = acc;
    __syncthreads();

    if (warp == 0) {
        acc = (lane < NTHREADS / 32) ? smem[lane] : 0.0f;
        #pragma unroll
        for (int off = 4; off > 0; off >>= 1)
            acc += __shfl_down_sync(0xFFFFFFFFu, acc, off);
        if (lane == 0) {
            g_partials[blockIdx.x] = acc;
            __threadfence();
            unsigned int t = atomicAdd(&g_ticket, 1u);
            s_is_last = (t == (unsigned int)(gridDim.x - 1));
        }
    }
    __syncthreads();

    if (!s_is_last) return;

    // Last block: reduce all NBLOCKS partials in a fixed order (deterministic).
    // Volatile loads bypass L1 so we see values published through L2.
    const volatile float* vp = (const volatile float*)g_partials;
    float tacc = 0.0f;
    for (int j = threadIdx.x; j < NBLOCKS; j += NTHREADS)
        tacc += vp[j];

    #pragma unroll
    for (int off = 16; off > 0; off >>= 1)
        tacc += __shfl_down_sync(0xFFFFFFFFu, tacc, off);

    if (lane == 0) smem[warp] = tacc;
    __syncthreads();

    if (warp == 0) {
        tacc = (lane < NTHREADS / 32) ? smem[lane] : 0.0f;
        #pragma unroll
        for (int off = 4; off > 0; off >>= 1)
            tacc += __shfl_down_sync(0xFFFFFFFFu, tacc, off);
        if (lane == 0) {
            out[0] = tacc * scale;
            g_ticket = 0;           // reset for next graph replay
            __threadfence();
        }
    }
}

extern "C" void kernel_launch(void* const* d_in, const int* in_sizes, int n_in,
                              void* d_out, int out_size)
{
    const float* p_mu = (const float*)d_in[0];
    const float* p_lv = (const float*)d_in[1];
    const float* q_mu = (const float*)d_in[2];
    const float* q_lv = (const float*)d_in[3];
    float* out = (float*)d_out;

    int n  = in_sizes[0];     // B*D
    int n4 = n >> 2;
    int B  = n / 512;         // D = 512
    float scale = 0.5f / (float)B;

    kl_fused_kernel<<<NBLOCKS, NTHREADS>>>(p_mu, p_lv, q_mu, q_lv, out, n4, scale);
}